// round 4
// baseline (speedup 1.0000x reference)
#include <cuda_runtime.h>
#include <cuda_bf16.h>
#include <stdint.h>
#include <math.h>

#define B_  8
#define S_  1024
#define D_  1024
#define H_  16
#define DH_ 64
#define M_  (B_*S_)     // 8192

// Split bf16 scratch planes (hi/lo) — no runtime allocation
__device__ __nv_bfloat16 g_qh[(size_t)M_*D_], g_ql[(size_t)M_*D_];
__device__ __nv_bfloat16 g_kh[(size_t)M_*D_], g_kl[(size_t)M_*D_];
__device__ __nv_bfloat16 g_vh[(size_t)M_*D_], g_vl[(size_t)M_*D_];
__device__ __nv_bfloat16 g_ch[(size_t)M_*D_], g_cl[(size_t)M_*D_];

// ---------------------------------------------------------------------------
// helpers
// ---------------------------------------------------------------------------
__device__ __forceinline__ uint32_t cvta_s(const void* p) {
    return (uint32_t)__cvta_generic_to_shared(p);
}
__device__ __forceinline__ void ldsm4(uint32_t r[4], uint32_t a) {
    asm volatile("ldmatrix.sync.aligned.m8n8.x4.shared.b16 {%0,%1,%2,%3}, [%4];"
        : "=r"(r[0]), "=r"(r[1]), "=r"(r[2]), "=r"(r[3]) : "r"(a));
}
__device__ __forceinline__ void ldsm4t(uint32_t r[4], uint32_t a) {
    asm volatile("ldmatrix.sync.aligned.m8n8.x4.trans.shared.b16 {%0,%1,%2,%3}, [%4];"
        : "=r"(r[0]), "=r"(r[1]), "=r"(r[2]), "=r"(r[3]) : "r"(a));
}
__device__ __forceinline__ void mma_bf(float c[4], const uint32_t a[4],
                                       uint32_t b0, uint32_t b1) {
    asm volatile("mma.sync.aligned.m16n8k16.row.col.f32.bf16.bf16.f32 "
        "{%0,%1,%2,%3},{%4,%5,%6,%7},{%8,%9},{%0,%1,%2,%3};"
        : "+f"(c[0]), "+f"(c[1]), "+f"(c[2]), "+f"(c[3])
        : "r"(a[0]), "r"(a[1]), "r"(a[2]), "r"(a[3]), "r"(b0), "r"(b1));
}
__device__ __forceinline__ void split_bf(float x, __nv_bfloat16& h, __nv_bfloat16& l) {
    h = __float2bfloat16(x);
    l = __float2bfloat16(x - __bfloat162float(h));
}

// ---------------------------------------------------------------------------
// Tensor-core GEMM: C = epi(A[8192,1024] @ W[1024,1024] + bias)
// 128x128 block tile, K-slab 32, 8 warps, warp tile 32x64.
// ---------------------------------------------------------------------------
template<bool DO_BN, bool SPLIT_OUT, bool A_SPLIT>
__global__ void __launch_bounds__(256)
gemm_tc(const float* __restrict__ Af,
        const __nv_bfloat16* __restrict__ Ahg, const __nv_bfloat16* __restrict__ Alg,
        const float* __restrict__ W, const float* __restrict__ bias,
        const float* __restrict__ gam, const float* __restrict__ bet,
        const float* __restrict__ mmean, const float* __restrict__ mvar,
        float* __restrict__ Cf,
        __nv_bfloat16* __restrict__ Chg, __nv_bfloat16* __restrict__ Clg)
{
    __shared__ __align__(16) __nv_bfloat16 sAh[128*40], sAl[128*40];
    __shared__ __align__(16) __nv_bfloat16 sBh[32*136], sBl[32*136];

    const int tid = threadIdx.x, lane = tid & 31, warp = tid >> 5;
    const int brow = blockIdx.y * 128, bcol = blockIdx.x * 128;

    float4 stA[4]; uint4 stAh[2], stAl[2]; float4 stB[4];

    auto loadG = [&](int ks) {
        if constexpr (!A_SPLIT) {
            #pragma unroll
            for (int p = 0; p < 4; p++) {
                int row = (tid >> 3) + 32 * p, col = (tid & 7) * 4;
                stA[p] = *(const float4*)&Af[(size_t)(brow + row) * D_ + ks + col];
            }
        } else {
            #pragma unroll
            for (int p = 0; p < 2; p++) {
                int idx = tid + 256 * p; int row = idx >> 2, ch = (idx & 3) * 8;
                stAh[p] = *(const uint4*)&Ahg[(size_t)(brow + row) * D_ + ks + ch];
                stAl[p] = *(const uint4*)&Alg[(size_t)(brow + row) * D_ + ks + ch];
            }
        }
        #pragma unroll
        for (int p = 0; p < 4; p++) {
            int row = (tid >> 5) + 8 * p, col = (tid & 31) * 4;
            stB[p] = *(const float4*)&W[(size_t)(ks + row) * D_ + bcol + col];
        }
    };
    auto storeS = [&]() {
        if constexpr (!A_SPLIT) {
            #pragma unroll
            for (int p = 0; p < 4; p++) {
                int row = (tid >> 3) + 32 * p, col = (tid & 7) * 4;
                float v[4] = {stA[p].x, stA[p].y, stA[p].z, stA[p].w};
                __nv_bfloat16 h[4], l[4];
                #pragma unroll
                for (int i = 0; i < 4; i++) split_bf(v[i], h[i], l[i]);
                *(__nv_bfloat162*)&sAh[row*40 + col]     = __halves2bfloat162(h[0], h[1]);
                *(__nv_bfloat162*)&sAh[row*40 + col + 2] = __halves2bfloat162(h[2], h[3]);
                *(__nv_bfloat162*)&sAl[row*40 + col]     = __halves2bfloat162(l[0], l[1]);
                *(__nv_bfloat162*)&sAl[row*40 + col + 2] = __halves2bfloat162(l[2], l[3]);
            }
        } else {
            #pragma unroll
            for (int p = 0; p < 2; p++) {
                int idx = tid + 256 * p; int row = idx >> 2, ch = (idx & 3) * 8;
                *(uint4*)&sAh[row*40 + ch] = stAh[p];
                *(uint4*)&sAl[row*40 + ch] = stAl[p];
            }
        }
        #pragma unroll
        for (int p = 0; p < 4; p++) {
            int row = (tid >> 5) + 8 * p, col = (tid & 31) * 4;
            float v[4] = {stB[p].x, stB[p].y, stB[p].z, stB[p].w};
            __nv_bfloat16 h[4], l[4];
            #pragma unroll
            for (int i = 0; i < 4; i++) split_bf(v[i], h[i], l[i]);
            *(__nv_bfloat162*)&sBh[row*136 + col]     = __halves2bfloat162(h[0], h[1]);
            *(__nv_bfloat162*)&sBh[row*136 + col + 2] = __halves2bfloat162(h[2], h[3]);
            *(__nv_bfloat162*)&sBl[row*136 + col]     = __halves2bfloat162(l[0], l[1]);
            *(__nv_bfloat162*)&sBl[row*136 + col + 2] = __halves2bfloat162(l[2], l[3]);
        }
    };

    const int wm = warp >> 1, wn = warp & 1;
    const int m0 = wm * 32, n0 = wn * 64;

    float acc[2][8][4];
    #pragma unroll
    for (int i = 0; i < 2; i++)
        #pragma unroll
        for (int j = 0; j < 8; j++)
            #pragma unroll
            for (int q = 0; q < 4; q++) acc[i][j][q] = 0.f;

    loadG(0);
    for (int ks = 0; ks < D_; ks += 32) {
        storeS();
        __syncthreads();
        if (ks + 32 < D_) loadG(ks + 32);

        #pragma unroll
        for (int kk = 0; kk < 32; kk += 16) {
            uint32_t ah[2][4], al[2][4];
            #pragma unroll
            for (int mi = 0; mi < 2; mi++) {
                int off = (m0 + mi*16 + (lane & 15)) * 40 + kk + ((lane >> 4) << 3);
                ldsm4(ah[mi], cvta_s(&sAh[off]));
                ldsm4(al[mi], cvta_s(&sAl[off]));
            }
            #pragma unroll
            for (int nj = 0; nj < 4; nj++) {
                uint32_t bh[4], bl[4];
                int off = (kk + (lane & 15)) * 136 + n0 + nj*16 + ((lane >> 4) << 3);
                ldsm4t(bh, cvta_s(&sBh[off]));
                ldsm4t(bl, cvta_s(&sBl[off]));
                #pragma unroll
                for (int mi = 0; mi < 2; mi++) {
                    mma_bf(acc[mi][2*nj],   ah[mi], bh[0], bh[1]);
                    mma_bf(acc[mi][2*nj],   ah[mi], bl[0], bl[1]);
                    mma_bf(acc[mi][2*nj],   al[mi], bh[0], bh[1]);
                    mma_bf(acc[mi][2*nj+1], ah[mi], bh[2], bh[3]);
                    mma_bf(acc[mi][2*nj+1], ah[mi], bl[2], bl[3]);
                    mma_bf(acc[mi][2*nj+1], al[mi], bh[2], bh[3]);
                }
            }
        }
        __syncthreads();
    }

    #pragma unroll
    for (int mi = 0; mi < 2; mi++) {
        int r0 = brow + m0 + mi*16 + (lane >> 2);
        #pragma unroll
        for (int nj = 0; nj < 8; nj++) {
            int c = bcol + n0 + nj*8 + (lane & 3)*2;
            float b0v = bias[c], b1v = bias[c+1];
            float sc0 = 1.f, sh0 = 0.f, sc1 = 1.f, sh1 = 0.f;
            if (DO_BN) {
                sc0 = gam[c]   * rsqrtf(mvar[c]   + 1e-3f); sh0 = bet[c]   - mmean[c]   * sc0;
                sc1 = gam[c+1] * rsqrtf(mvar[c+1] + 1e-3f); sh1 = bet[c+1] - mmean[c+1] * sc1;
            }
            float y00 = fmaxf(acc[mi][nj][0] + b0v, 0.f);
            float y01 = fmaxf(acc[mi][nj][1] + b1v, 0.f);
            float y10 = fmaxf(acc[mi][nj][2] + b0v, 0.f);
            float y11 = fmaxf(acc[mi][nj][3] + b1v, 0.f);
            if (DO_BN) {
                y00 = y00*sc0 + sh0; y01 = y01*sc1 + sh1;
                y10 = y10*sc0 + sh0; y11 = y11*sc1 + sh1;
            }
            if constexpr (SPLIT_OUT) {
                __nv_bfloat16 h0,l0,h1,l1,h2,l2,h3,l3;
                split_bf(y00,h0,l0); split_bf(y01,h1,l1);
                split_bf(y10,h2,l2); split_bf(y11,h3,l3);
                *(__nv_bfloat162*)&Chg[(size_t)r0*D_ + c]     = __halves2bfloat162(h0,h1);
                *(__nv_bfloat162*)&Clg[(size_t)r0*D_ + c]     = __halves2bfloat162(l0,l1);
                *(__nv_bfloat162*)&Chg[(size_t)(r0+8)*D_ + c] = __halves2bfloat162(h2,h3);
                *(__nv_bfloat162*)&Clg[(size_t)(r0+8)*D_ + c] = __halves2bfloat162(l2,l3);
            } else {
                *(float2*)&Cf[(size_t)r0*D_ + c]     = make_float2(y00, y01);
                *(float2*)&Cf[(size_t)(r0+8)*D_ + c] = make_float2(y10, y11);
            }
        }
    }
}

// ---------------------------------------------------------------------------
// Fused attention: per CTA = 32 query rows of one (b,h).
//   phase 1: scores = (Q Kh^T)*0.125 + mask  -> split bf16 planes in smem
//   softmax in smem, write normalized attn (fp32) to gmem ONCE
//   phase 2: ctx = P @ V  -> split bf16 to g_ch/g_cl
// smem plane stride 1048 (conflict-free ldmatrix). Total smem 184320 B.
// ---------------------------------------------------------------------------
#define PSTR 1048
__global__ void __launch_bounds__(256)
attn_fused(const float* __restrict__ mask, float* __restrict__ attn)
{
    extern __shared__ __align__(16) char smb[];
    __nv_bfloat16* sPh = (__nv_bfloat16*)(smb);              // [32][PSTR]
    __nv_bfloat16* sPl = (__nv_bfloat16*)(smb + 67072);
    __nv_bfloat16* sTh = (__nv_bfloat16*)(smb + 134144);     // [128][72] K/V tile hi
    __nv_bfloat16* sTl = (__nv_bfloat16*)(smb + 152576);     // lo
    __nv_bfloat16* sQh = (__nv_bfloat16*)(smb + 171008);     // [32][72]
    __nv_bfloat16* sQl = (__nv_bfloat16*)(smb + 175616);
    float*         msk = (float*)(smb + 180224);             // [1024]

    const int bh = blockIdx.y, b = bh >> 4, h = bh & 15;
    const int brow = blockIdx.x * 32;
    const size_t base = (size_t)b * S_ * D_ + h * DH_;
    const int tid = threadIdx.x, lane = tid & 31, warp = tid >> 5;

    // Q tile (32x64 hi/lo): 256 uint4 per plane, 1 per thread
    {
        int row = tid >> 3, ch = (tid & 7) * 8;
        *(uint4*)&sQh[row*72 + ch] = *(const uint4*)&g_qh[base + (size_t)(brow + row)*D_ + ch];
        *(uint4*)&sQl[row*72 + ch] = *(const uint4*)&g_ql[base + (size_t)(brow + row)*D_ + ch];
    }
    {
        float4 mv = *(const float4*)&mask[b*S_ + tid*4];
        *(float4*)&msk[tid*4] = make_float4(mv.x * -1e9f, mv.y * -1e9f,
                                            mv.z * -1e9f, mv.w * -1e9f);
    }

    const int wm = warp >> 2;        // 0..1  (16 rows each)
    const int wn = warp & 3;         // 0..3
    const int m0 = wm * 16;

    uint4 stH[4], stL[4];
    auto loadT = [&](const __nv_bfloat16* __restrict__ gh,
                     const __nv_bfloat16* __restrict__ gl, int t) {
        #pragma unroll
        for (int p = 0; p < 4; p++) {
            int idx = tid + 256 * p;           // 0..1023
            int r = idx >> 3, ch = (idx & 7) * 8;
            stH[p] = *(const uint4*)&gh[base + (size_t)(t*128 + r)*D_ + ch];
            stL[p] = *(const uint4*)&gl[base + (size_t)(t*128 + r)*D_ + ch];
        }
    };
    auto storeT = [&]() {
        #pragma unroll
        for (int p = 0; p < 4; p++) {
            int idx = tid + 256 * p;
            int r = idx >> 3, ch = (idx & 7) * 8;
            *(uint4*)&sTh[r*72 + ch] = stH[p];
            *(uint4*)&sTl[r*72 + ch] = stL[p];
        }
    };

    // ---- phase 1: scores ----
    loadT(g_kh, g_kl, 0);
    for (int kt = 0; kt < 8; kt++) {
        storeT();
        __syncthreads();
        if (kt < 7) loadT(g_kh, g_kl, kt + 1);

        float acc[4][4] = {};
        #pragma unroll
        for (int kk = 0; kk < 64; kk += 16) {
            uint32_t ah[4], al[4];
            int offA = (m0 + (lane & 15)) * 72 + kk + ((lane >> 4) << 3);
            ldsm4(ah, cvta_s(&sQh[offA]));
            ldsm4(al, cvta_s(&sQl[offA]));
            #pragma unroll
            for (int nj = 0; nj < 2; nj++) {
                int nr = wn*32 + nj*16 + ((lane & 7) | (((lane >> 4) & 1) << 3));
                int offB = nr * 72 + kk + (((lane >> 3) & 1) << 3);
                uint32_t bhf[4], blf[4];
                ldsm4(bhf, cvta_s(&sTh[offB]));
                ldsm4(blf, cvta_s(&sTl[offB]));
                mma_bf(acc[2*nj],   ah, bhf[0], bhf[1]);
                mma_bf(acc[2*nj],   ah, blf[0], blf[1]);
                mma_bf(acc[2*nj],   al, bhf[0], bhf[1]);
                mma_bf(acc[2*nj+1], ah, bhf[2], bhf[3]);
                mma_bf(acc[2*nj+1], ah, blf[2], blf[3]);
                mma_bf(acc[2*nj+1], al, bhf[2], bhf[3]);
            }
        }
        // scale + mask, split-store into planes
        int r0 = m0 + (lane >> 2);
        #pragma unroll
        for (int c8 = 0; c8 < 4; c8++) {
            int c = kt*128 + wn*32 + c8*8 + (lane & 3)*2;
            float mv0 = msk[c], mv1 = msk[c+1];
            float x0 = acc[c8][0]*0.125f + mv0;
            float x1 = acc[c8][1]*0.125f + mv1;
            float x2 = acc[c8][2]*0.125f + mv0;
            float x3 = acc[c8][3]*0.125f + mv1;
            __nv_bfloat16 h0,l0,h1,l1;
            split_bf(x0,h0,l0); split_bf(x1,h1,l1);
            *(__nv_bfloat162*)&sPh[r0*PSTR + c] = __halves2bfloat162(h0,h1);
            *(__nv_bfloat162*)&sPl[r0*PSTR + c] = __halves2bfloat162(l0,l1);
            split_bf(x2,h0,l0); split_bf(x3,h1,l1);
            *(__nv_bfloat162*)&sPh[(r0+8)*PSTR + c] = __halves2bfloat162(h0,h1);
            *(__nv_bfloat162*)&sPl[(r0+8)*PSTR + c] = __halves2bfloat162(l0,l1);
        }
        __syncthreads();
    }

    // prefetch V tile 0 while softmax runs
    loadT(g_vh, g_vl, 0);

    // ---- softmax: 8 threads per row, 128 cols each (strided float4 pattern) ----
    {
        const int srow = tid >> 3, seg = tid & 7;
        const int rb = srow * PSTR;

        float mx = -3.4e38f;
        #pragma unroll 8
        for (int j = 0; j < 32; j++) {
            int c = j*32 + seg*4;
            __nv_bfloat162 ha = *(__nv_bfloat162*)&sPh[rb + c];
            __nv_bfloat162 hb = *(__nv_bfloat162*)&sPh[rb + c + 2];
            __nv_bfloat162 la = *(__nv_bfloat162*)&sPl[rb + c];
            __nv_bfloat162 lb = *(__nv_bfloat162*)&sPl[rb + c + 2];
            mx = fmaxf(mx, __bfloat162float(ha.x) + __bfloat162float(la.x));
            mx = fmaxf(mx, __bfloat162float(ha.y) + __bfloat162float(la.y));
            mx = fmaxf(mx, __bfloat162float(hb.x) + __bfloat162float(lb.x));
            mx = fmaxf(mx, __bfloat162float(hb.y) + __bfloat162float(lb.y));
        }
        #pragma unroll
        for (int o = 1; o < 8; o <<= 1) mx = fmaxf(mx, __shfl_xor_sync(0xffffffffu, mx, o));

        float s = 0.f;
        #pragma unroll 8
        for (int j = 0; j < 32; j++) {
            int c = j*32 + seg*4;
            __nv_bfloat162 ha = *(__nv_bfloat162*)&sPh[rb + c];
            __nv_bfloat162 hb = *(__nv_bfloat162*)&sPh[rb + c + 2];
            __nv_bfloat162 la = *(__nv_bfloat162*)&sPl[rb + c];
            __nv_bfloat162 lb = *(__nv_bfloat162*)&sPl[rb + c + 2];
            s += __expf(__bfloat162float(ha.x) + __bfloat162float(la.x) - mx);
            s += __expf(__bfloat162float(ha.y) + __bfloat162float(la.y) - mx);
            s += __expf(__bfloat162float(hb.x) + __bfloat162float(lb.x) - mx);
            s += __expf(__bfloat162float(hb.y) + __bfloat162float(lb.y) - mx);
        }
        #pragma unroll
        for (int o = 1; o < 8; o <<= 1) s += __shfl_xor_sync(0xffffffffu, s, o);
        const float inv = 1.f / s;

        float* outp = attn + (size_t)bh * S_ * S_ + (size_t)(brow + srow) * S_;
        #pragma unroll 8
        for (int j = 0; j < 32; j++) {
            int c = j*32 + seg*4;
            __nv_bfloat162 ha = *(__nv_bfloat162*)&sPh[rb + c];
            __nv_bfloat162 hb = *(__nv_bfloat162*)&sPh[rb + c + 2];
            __nv_bfloat162 la = *(__nv_bfloat162*)&sPl[rb + c];
            __nv_bfloat162 lb = *(__nv_bfloat162*)&sPl[rb + c + 2];
            float p0 = __expf(__bfloat162float(ha.x) + __bfloat162float(la.x) - mx) * inv;
            float p1 = __expf(__bfloat162float(ha.y) + __bfloat162float(la.y) - mx) * inv;
            float p2 = __expf(__bfloat162float(hb.x) + __bfloat162float(lb.x) - mx) * inv;
            float p3 = __expf(__bfloat162float(hb.y) + __bfloat162float(lb.y) - mx) * inv;
            *(float4*)&outp[c] = make_float4(p0, p1, p2, p3);
            __nv_bfloat16 h0,l0,h1,l1;
            split_bf(p0,h0,l0); split_bf(p1,h1,l1);
            *(__nv_bfloat162*)&sPh[rb + c]     = __halves2bfloat162(h0,h1);
            *(__nv_bfloat162*)&sPl[rb + c]     = __halves2bfloat162(l0,l1);
            split_bf(p2,h0,l0); split_bf(p3,h1,l1);
            *(__nv_bfloat162*)&sPh[rb + c + 2] = __halves2bfloat162(h0,h1);
            *(__nv_bfloat162*)&sPl[rb + c + 2] = __halves2bfloat162(l0,l1);
        }
    }
    __syncthreads();

    // ---- phase 2: ctx = P @ V ----
    const int n0 = wn * 16;
    float cacc[2][4] = {};
    for (int vt = 0; vt < 8; vt++) {
        storeT();
        __syncthreads();
        if (vt < 7) loadT(g_vh, g_vl, vt + 1);

        #pragma unroll
        for (int kk = 0; kk < 128; kk += 16) {
            uint32_t ah[4], al[4];
            int offA = (m0 + (lane & 15)) * PSTR + vt*128 + kk + ((lane >> 4) << 3);
            ldsm4(ah, cvta_s(&sPh[offA]));
            ldsm4(al, cvta_s(&sPl[offA]));
            uint32_t bhf[4], blf[4];
            int offB = (kk + (lane & 15)) * 72 + n0 + ((lane >> 4) << 3);
            ldsm4t(bhf, cvta_s(&sTh[offB]));
            ldsm4t(blf, cvta_s(&sTl[offB]));
            mma_bf(cacc[0], ah, bhf[0], bhf[1]);
            mma_bf(cacc[0], ah, blf[0], blf[1]);
            mma_bf(cacc[0], al, bhf[0], bhf[1]);
            mma_bf(cacc[1], ah, bhf[2], bhf[3]);
            mma_bf(cacc[1], ah, blf[2], blf[3]);
            mma_bf(cacc[1], al, bhf[2], bhf[3]);
        }
        __syncthreads();
    }

    // write ctx split bf16
    {
        __nv_bfloat16* Ch = g_ch + base;
        __nv_bfloat16* Cl = g_cl + base;
        int r0 = brow + m0 + (lane >> 2);
        #pragma unroll
        for (int nj = 0; nj < 2; nj++) {
            int c = n0 + nj*8 + (lane & 3)*2;
            __nv_bfloat16 h0,l0,h1,l1,h2,l2,h3,l3;
            split_bf(cacc[nj][0], h0, l0); split_bf(cacc[nj][1], h1, l1);
            split_bf(cacc[nj][2], h2, l2); split_bf(cacc[nj][3], h3, l3);
            *(__nv_bfloat162*)&Ch[(size_t)r0*D_ + c]     = __halves2bfloat162(h0, h1);
            *(__nv_bfloat162*)&Cl[(size_t)r0*D_ + c]     = __halves2bfloat162(l0, l1);
            *(__nv_bfloat162*)&Ch[(size_t)(r0+8)*D_ + c] = __halves2bfloat162(h2, h3);
            *(__nv_bfloat162*)&Cl[(size_t)(r0+8)*D_ + c] = __halves2bfloat162(l2, l3);
        }
    }
}

// ---------------------------------------------------------------------------
extern "C" void kernel_launch(void* const* d_in, const int* in_sizes, int n_in,
                              void* d_out, int out_size)
{
    const float* q    = (const float*)d_in[0];
    const float* k    = (const float*)d_in[1];
    const float* v    = (const float*)d_in[2];
    const float* mask = (const float*)d_in[3];
    const float* wq = (const float*)d_in[4];  const float* bq = (const float*)d_in[5];
    const float* wk = (const float*)d_in[6];  const float* bk = (const float*)d_in[7];
    const float* wv = (const float*)d_in[8];  const float* bv = (const float*)d_in[9];
    const float* wo = (const float*)d_in[10]; const float* bo = (const float*)d_in[11];
    const float* g1 = (const float*)d_in[12]; const float* be1 = (const float*)d_in[13];
    const float* mm1 = (const float*)d_in[14]; const float* mv1 = (const float*)d_in[15];
    const float* g2 = (const float*)d_in[16]; const float* be2 = (const float*)d_in[17];
    const float* mm2 = (const float*)d_in[18]; const float* mv2 = (const float*)d_in[19];
    const float* g3 = (const float*)d_in[20]; const float* be3 = (const float*)d_in[21];
    const float* mm3 = (const float*)d_in[22]; const float* mv3 = (const float*)d_in[23];

    float* out  = (float*)d_out;
    float* attn = out + (size_t)M_ * D_;

    void* p;
    __nv_bfloat16 *qh,*ql,*kh,*kl,*vh,*vl,*ch,*cl;
    cudaGetSymbolAddress(&p, g_qh); qh = (__nv_bfloat16*)p;
    cudaGetSymbolAddress(&p, g_ql); ql = (__nv_bfloat16*)p;
    cudaGetSymbolAddress(&p, g_kh); kh = (__nv_bfloat16*)p;
    cudaGetSymbolAddress(&p, g_kl); kl = (__nv_bfloat16*)p;
    cudaGetSymbolAddress(&p, g_vh); vh = (__nv_bfloat16*)p;
    cudaGetSymbolAddress(&p, g_vl); vl = (__nv_bfloat16*)p;
    cudaGetSymbolAddress(&p, g_ch); ch = (__nv_bfloat16*)p;
    cudaGetSymbolAddress(&p, g_cl); cl = (__nv_bfloat16*)p;

    dim3 gp(D_/128, M_/128);   // (8, 64)
    gemm_tc<true,true,false><<<gp,256>>>(q, nullptr, nullptr, wq, bq, g1, be1, mm1, mv1,
                                         nullptr, qh, ql);
    gemm_tc<true,true,false><<<gp,256>>>(k, nullptr, nullptr, wk, bk, g2, be2, mm2, mv2,
                                         nullptr, kh, kl);
    gemm_tc<true,true,false><<<gp,256>>>(v, nullptr, nullptr, wv, bv, g3, be3, mm3, mv3,
                                         nullptr, vh, vl);

    cudaFuncSetAttribute(attn_fused, cudaFuncAttributeMaxDynamicSharedMemorySize, 184320);
    attn_fused<<<dim3(32,128),256,184320>>>(mask, attn);

    gemm_tc<false,false,true><<<gp,256>>>(nullptr, ch, cl, wo, bo,
                                          nullptr, nullptr, nullptr, nullptr,
                                          out, nullptr, nullptr);
}

// round 5
// speedup vs baseline: 1.1578x; 1.1578x over previous
#include <cuda_runtime.h>
#include <cuda_bf16.h>
#include <stdint.h>
#include <math.h>

#define B_  8
#define S_  1024
#define D_  1024
#define H_  16
#define DH_ 64
#define M_  (B_*S_)     // 8192

// Projected split planes
__device__ __nv_bfloat16 g_qh[(size_t)M_*D_], g_ql[(size_t)M_*D_];
__device__ __nv_bfloat16 g_kh[(size_t)M_*D_], g_kl[(size_t)M_*D_];
__device__ __nv_bfloat16 g_vh[(size_t)M_*D_], g_vl[(size_t)M_*D_];
__device__ __nv_bfloat16 g_ch[(size_t)M_*D_], g_cl[(size_t)M_*D_];
// Raw-input split planes
__device__ __nv_bfloat16 g_rqh[(size_t)M_*D_], g_rql[(size_t)M_*D_];
__device__ __nv_bfloat16 g_rkh[(size_t)M_*D_], g_rkl[(size_t)M_*D_];
__device__ __nv_bfloat16 g_rvh[(size_t)M_*D_], g_rvl[(size_t)M_*D_];
// Weight split planes (wq, wk, wv, wo)
__device__ __nv_bfloat16 g_wh[4][(size_t)D_*D_], g_wl[4][(size_t)D_*D_];

// ---------------------------------------------------------------------------
__device__ __forceinline__ uint32_t cvta_s(const void* p) {
    return (uint32_t)__cvta_generic_to_shared(p);
}
__device__ __forceinline__ void cpa16(uint32_t dst, const void* src) {
    asm volatile("cp.async.cg.shared.global [%0], [%1], 16;" :: "r"(dst), "l"(src));
}
__device__ __forceinline__ void ldsm4(uint32_t r[4], uint32_t a) {
    asm volatile("ldmatrix.sync.aligned.m8n8.x4.shared.b16 {%0,%1,%2,%3}, [%4];"
        : "=r"(r[0]), "=r"(r[1]), "=r"(r[2]), "=r"(r[3]) : "r"(a));
}
__device__ __forceinline__ void ldsm4t(uint32_t r[4], uint32_t a) {
    asm volatile("ldmatrix.sync.aligned.m8n8.x4.trans.shared.b16 {%0,%1,%2,%3}, [%4];"
        : "=r"(r[0]), "=r"(r[1]), "=r"(r[2]), "=r"(r[3]) : "r"(a));
}
__device__ __forceinline__ void mma_bf(float c[4], const uint32_t a[4],
                                       uint32_t b0, uint32_t b1) {
    asm volatile("mma.sync.aligned.m16n8k16.row.col.f32.bf16.bf16.f32 "
        "{%0,%1,%2,%3},{%4,%5,%6,%7},{%8,%9},{%0,%1,%2,%3};"
        : "+f"(c[0]), "+f"(c[1]), "+f"(c[2]), "+f"(c[3])
        : "r"(a[0]), "r"(a[1]), "r"(a[2]), "r"(a[3]), "r"(b0), "r"(b1));
}
__device__ __forceinline__ void split_bf(float x, __nv_bfloat16& h, __nv_bfloat16& l) {
    h = __float2bfloat16(x);
    l = __float2bfloat16(x - __bfloat162float(h));
}

// ---------------------------------------------------------------------------
// Pre-split: fp32 -> bf16 hi/lo planes (vectorized)
// ---------------------------------------------------------------------------
__global__ void __launch_bounds__(256)
split_kernel(const float* __restrict__ in, __nv_bfloat16* __restrict__ hi,
             __nv_bfloat16* __restrict__ lo, int n4)
{
    int i = blockIdx.x * blockDim.x + threadIdx.x;
    if (i >= n4) return;
    float4 v = ((const float4*)in)[i];
    __nv_bfloat16 h0,l0,h1,l1,h2,l2,h3,l3;
    split_bf(v.x,h0,l0); split_bf(v.y,h1,l1);
    split_bf(v.z,h2,l2); split_bf(v.w,h3,l3);
    ((__nv_bfloat162*)hi)[2*i]   = __halves2bfloat162(h0,h1);
    ((__nv_bfloat162*)hi)[2*i+1] = __halves2bfloat162(h2,h3);
    ((__nv_bfloat162*)lo)[2*i]   = __halves2bfloat162(l0,l1);
    ((__nv_bfloat162*)lo)[2*i+1] = __halves2bfloat162(l2,l3);
}

// ---------------------------------------------------------------------------
// All-split tensor-core GEMM with cp.async double buffering.
// C = epi(A[8192,1024] @ W[1024,1024] + bias); A,W as bf16 hi/lo planes.
// 128x128 tile, BK=32, 8 warps (warp tile 32x64), 2-stage pipeline.
// smem stage layout (bf16 elems): Ah[128*40]@0, Al@5120, Bh[32*136]@10240, Bl@14592
// ---------------------------------------------------------------------------
#define STG_ 18944
template<bool DO_BN, bool SPLIT_OUT>
__global__ void __launch_bounds__(256)
gemm_tc2(const __nv_bfloat16* __restrict__ Ah, const __nv_bfloat16* __restrict__ Al,
         const __nv_bfloat16* __restrict__ Wh, const __nv_bfloat16* __restrict__ Wl,
         const float* __restrict__ bias,
         const float* __restrict__ gam, const float* __restrict__ bet,
         const float* __restrict__ mmean, const float* __restrict__ mvar,
         float* __restrict__ Cf,
         __nv_bfloat16* __restrict__ Chg, __nv_bfloat16* __restrict__ Clg)
{
    extern __shared__ __align__(16) __nv_bfloat16 sm2[];
    const int tid = threadIdx.x, lane = tid & 31, warp = tid >> 5;
    const int brow = blockIdx.y * 128, bcol = blockIdx.x * 128;

    auto issue = [&](int slab, int buf) {
        __nv_bfloat16* st = sm2 + buf * STG_;
        const int ks = slab * 32;
        #pragma unroll
        for (int p = 0; p < 2; p++) {
            int c = tid + 256 * p;             // 0..511
            int r = c >> 2, q = (c & 3) * 8;   // row 0..127, col elem 0..24
            const size_t ga = (size_t)(brow + r) * D_ + ks + q;
            cpa16(cvta_s(&st[r*40 + q]),        &Ah[ga]);
            cpa16(cvta_s(&st[5120 + r*40 + q]), &Al[ga]);
        }
        #pragma unroll
        for (int p = 0; p < 2; p++) {
            int c = tid + 256 * p;
            int r = c >> 4, q = (c & 15) * 8;  // row 0..31, col elem 0..120
            const size_t gb = (size_t)(ks + r) * D_ + bcol + q;
            cpa16(cvta_s(&st[10240 + r*136 + q]), &Wh[gb]);
            cpa16(cvta_s(&st[14592 + r*136 + q]), &Wl[gb]);
        }
        asm volatile("cp.async.commit_group;");
    };

    const int wm = warp >> 1, wn = warp & 1;
    const int m0 = wm * 32, n0 = wn * 64;

    float acc[2][8][4];
    #pragma unroll
    for (int i = 0; i < 2; i++)
        #pragma unroll
        for (int j = 0; j < 8; j++)
            #pragma unroll
            for (int q = 0; q < 4; q++) acc[i][j][q] = 0.f;

    issue(0, 0);
    for (int s = 0; s < 32; s++) {
        const int buf = s & 1;
        if (s + 1 < 32) {
            issue(s + 1, buf ^ 1);
            asm volatile("cp.async.wait_group 1;");
        } else {
            asm volatile("cp.async.wait_group 0;");
        }
        __syncthreads();

        const __nv_bfloat16* sAh = sm2 + buf * STG_;
        const __nv_bfloat16* sAl = sAh + 5120;
        const __nv_bfloat16* sBh = sAh + 10240;
        const __nv_bfloat16* sBl = sAh + 14592;

        #pragma unroll
        for (int kk = 0; kk < 32; kk += 16) {
            uint32_t ah[2][4], al[2][4];
            #pragma unroll
            for (int mi = 0; mi < 2; mi++) {
                int off = (m0 + mi*16 + (lane & 15)) * 40 + kk + ((lane >> 4) << 3);
                ldsm4(ah[mi], cvta_s(&sAh[off]));
                ldsm4(al[mi], cvta_s(&sAl[off]));
            }
            #pragma unroll
            for (int nj = 0; nj < 4; nj++) {
                uint32_t bh[4], bl[4];
                int off = (kk + (lane & 15)) * 136 + n0 + nj*16 + ((lane >> 4) << 3);
                ldsm4t(bh, cvta_s(&sBh[off]));
                ldsm4t(bl, cvta_s(&sBl[off]));
                #pragma unroll
                for (int mi = 0; mi < 2; mi++) {
                    mma_bf(acc[mi][2*nj],   ah[mi], bh[0], bh[1]);
                    mma_bf(acc[mi][2*nj],   ah[mi], bl[0], bl[1]);
                    mma_bf(acc[mi][2*nj],   al[mi], bh[0], bh[1]);
                    mma_bf(acc[mi][2*nj+1], ah[mi], bh[2], bh[3]);
                    mma_bf(acc[mi][2*nj+1], ah[mi], bl[2], bl[3]);
                    mma_bf(acc[mi][2*nj+1], al[mi], bh[2], bh[3]);
                }
            }
        }
        __syncthreads();
    }

    // epilogue
    #pragma unroll
    for (int mi = 0; mi < 2; mi++) {
        int r0 = brow + m0 + mi*16 + (lane >> 2);
        #pragma unroll
        for (int nj = 0; nj < 8; nj++) {
            int c = bcol + n0 + nj*8 + (lane & 3)*2;
            float b0v = bias[c], b1v = bias[c+1];
            float sc0 = 1.f, sh0 = 0.f, sc1 = 1.f, sh1 = 0.f;
            if (DO_BN) {
                sc0 = gam[c]   * rsqrtf(mvar[c]   + 1e-3f); sh0 = bet[c]   - mmean[c]   * sc0;
                sc1 = gam[c+1] * rsqrtf(mvar[c+1] + 1e-3f); sh1 = bet[c+1] - mmean[c+1] * sc1;
            }
            float y00 = fmaxf(acc[mi][nj][0] + b0v, 0.f);
            float y01 = fmaxf(acc[mi][nj][1] + b1v, 0.f);
            float y10 = fmaxf(acc[mi][nj][2] + b0v, 0.f);
            float y11 = fmaxf(acc[mi][nj][3] + b1v, 0.f);
            if (DO_BN) {
                y00 = y00*sc0 + sh0; y01 = y01*sc1 + sh1;
                y10 = y10*sc0 + sh0; y11 = y11*sc1 + sh1;
            }
            if constexpr (SPLIT_OUT) {
                __nv_bfloat16 h0,l0,h1,l1,h2,l2,h3,l3;
                split_bf(y00,h0,l0); split_bf(y01,h1,l1);
                split_bf(y10,h2,l2); split_bf(y11,h3,l3);
                *(__nv_bfloat162*)&Chg[(size_t)r0*D_ + c]     = __halves2bfloat162(h0,h1);
                *(__nv_bfloat162*)&Clg[(size_t)r0*D_ + c]     = __halves2bfloat162(l0,l1);
                *(__nv_bfloat162*)&Chg[(size_t)(r0+8)*D_ + c] = __halves2bfloat162(h2,h3);
                *(__nv_bfloat162*)&Clg[(size_t)(r0+8)*D_ + c] = __halves2bfloat162(l2,l3);
            } else {
                *(float2*)&Cf[(size_t)r0*D_ + c]     = make_float2(y00, y01);
                *(float2*)&Cf[(size_t)(r0+8)*D_ + c] = make_float2(y10, y11);
            }
        }
    }
}

// ---------------------------------------------------------------------------
// scores: per (b,h): (Qh @ Kh^T)*0.125 + mask*(-1e9)  [K=64, single load]
// ---------------------------------------------------------------------------
__global__ void __launch_bounds__(256)
scores_tc(const float* __restrict__ mask, float* __restrict__ attn)
{
    extern __shared__ __align__(16) __nv_bfloat16 sm[];
    __nv_bfloat16* sQh = sm;
    __nv_bfloat16* sQl = sm + 9216;
    __nv_bfloat16* sKh = sm + 18432;
    __nv_bfloat16* sKl = sm + 27648;

    const int bh = blockIdx.z, b = bh >> 4, h = bh & 15;
    const size_t base = (size_t)b * S_ * D_ + h * DH_;
    const int tid = threadIdx.x, lane = tid & 31, warp = tid >> 5;
    const int brow = blockIdx.y * 128, bcol = blockIdx.x * 128;

    #pragma unroll
    for (int p = 0; p < 4; p++) {
        int idx = tid + 256 * p;
        int row = idx >> 3;
        int ch  = (idx & 7) * 8;
        *(uint4*)&sQh[row*72 + ch] = *(const uint4*)&g_qh[base + (size_t)(brow + row)*D_ + ch];
        *(uint4*)&sQl[row*72 + ch] = *(const uint4*)&g_ql[base + (size_t)(brow + row)*D_ + ch];
        *(uint4*)&sKh[row*72 + ch] = *(const uint4*)&g_kh[base + (size_t)(bcol + row)*D_ + ch];
        *(uint4*)&sKl[row*72 + ch] = *(const uint4*)&g_kl[base + (size_t)(bcol + row)*D_ + ch];
    }
    __syncthreads();

    const int wm = warp >> 1, wn = warp & 1;
    const int m0 = wm * 32, n0 = wn * 64;

    float acc[2][8][4];
    #pragma unroll
    for (int i = 0; i < 2; i++)
        #pragma unroll
        for (int j = 0; j < 8; j++)
            #pragma unroll
            for (int q = 0; q < 4; q++) acc[i][j][q] = 0.f;

    #pragma unroll
    for (int kk = 0; kk < 64; kk += 16) {
        uint32_t ah[2][4], al[2][4];
        #pragma unroll
        for (int mi = 0; mi < 2; mi++) {
            int off = (m0 + mi*16 + (lane & 15)) * 72 + kk + ((lane >> 4) << 3);
            ldsm4(ah[mi], cvta_s(&sQh[off]));
            ldsm4(al[mi], cvta_s(&sQl[off]));
        }
        #pragma unroll
        for (int nj = 0; nj < 4; nj++) {
            int nr = n0 + nj*16 + ((lane & 7) | (((lane >> 4) & 1) << 3));
            int off = nr * 72 + kk + (((lane >> 3) & 1) << 3);
            uint32_t bh[4], bl[4];
            ldsm4(bh, cvta_s(&sKh[off]));
            ldsm4(bl, cvta_s(&sKl[off]));
            #pragma unroll
            for (int mi = 0; mi < 2; mi++) {
                mma_bf(acc[mi][2*nj],   ah[mi], bh[0], bh[1]);
                mma_bf(acc[mi][2*nj],   ah[mi], bl[0], bl[1]);
                mma_bf(acc[mi][2*nj],   al[mi], bh[0], bh[1]);
                mma_bf(acc[mi][2*nj+1], ah[mi], bh[2], bh[3]);
                mma_bf(acc[mi][2*nj+1], ah[mi], bl[2], bl[3]);
                mma_bf(acc[mi][2*nj+1], al[mi], bh[2], bh[3]);
            }
        }
    }

    float* outp = attn + (size_t)bh * S_ * S_;
    #pragma unroll
    for (int mi = 0; mi < 2; mi++) {
        int r0 = brow + m0 + mi*16 + (lane >> 2);
        #pragma unroll
        for (int nj = 0; nj < 8; nj++) {
            int c = bcol + n0 + nj*8 + (lane & 3)*2;
            float mv0 = mask[b*S_ + c]     * (-1e9f);
            float mv1 = mask[b*S_ + c + 1] * (-1e9f);
            *(float2*)&outp[(size_t)r0*S_ + c] =
                make_float2(acc[mi][nj][0]*0.125f + mv0, acc[mi][nj][1]*0.125f + mv1);
            *(float2*)&outp[(size_t)(r0+8)*S_ + c] =
                make_float2(acc[mi][nj][2]*0.125f + mv0, acc[mi][nj][3]*0.125f + mv1);
        }
    }
}

// ---------------------------------------------------------------------------
// In-place row softmax (1024 floats/row), 128 threads/row.
// ---------------------------------------------------------------------------
__global__ void __launch_bounds__(128)
softmax_kernel(float* __restrict__ attn)
{
    const size_t row = blockIdx.x;
    float* p = attn + row * (size_t)S_;
    const int tid = threadIdx.x, lane = tid & 31, warp = tid >> 5;

    float v[8];
    float4 a = *reinterpret_cast<const float4*>(&p[tid*8]);
    float4 c = *reinterpret_cast<const float4*>(&p[tid*8 + 4]);
    v[0]=a.x; v[1]=a.y; v[2]=a.z; v[3]=a.w;
    v[4]=c.x; v[5]=c.y; v[6]=c.z; v[7]=c.w;

    float mx = v[0];
    #pragma unroll
    for (int i = 1; i < 8; i++) mx = fmaxf(mx, v[i]);
    #pragma unroll
    for (int o = 16; o; o >>= 1) mx = fmaxf(mx, __shfl_xor_sync(0xffffffffu, mx, o));

    __shared__ float smax[4], ssum[4];
    if (lane == 0) smax[warp] = mx;
    __syncthreads();
    mx = fmaxf(fmaxf(smax[0], smax[1]), fmaxf(smax[2], smax[3]));

    float s = 0.f;
    #pragma unroll
    for (int i = 0; i < 8; i++) { v[i] = __expf(v[i] - mx); s += v[i]; }
    #pragma unroll
    for (int o = 16; o; o >>= 1) s += __shfl_xor_sync(0xffffffffu, s, o);
    if (lane == 0) ssum[warp] = s;
    __syncthreads();
    s = ssum[0] + ssum[1] + ssum[2] + ssum[3];

    const float inv = 1.f / s;
    *(float4*)&p[tid*8]     = make_float4(v[0]*inv, v[1]*inv, v[2]*inv, v[3]*inv);
    *(float4*)&p[tid*8 + 4] = make_float4(v[4]*inv, v[5]*inv, v[6]*inv, v[7]*inv);
}

// ---------------------------------------------------------------------------
// ctx = attn[bh] @ Vh -> split bf16 into g_ch/g_cl ([B,S,D] layout)
// ---------------------------------------------------------------------------
__global__ void __launch_bounds__(256)
ctx_tc(const float* __restrict__ attn)
{
    __shared__ __align__(16) __nv_bfloat16 sAh[128*40], sAl[128*40];
    __shared__ __align__(16) __nv_bfloat16 sBh[32*72],  sBl[32*72];

    const int bh = blockIdx.y, b = bh >> 4, h = bh & 15;
    const float* A = attn + (size_t)bh * S_ * S_;
    const __nv_bfloat16* Vh = g_vh + (size_t)b * S_ * D_ + h * DH_;
    const __nv_bfloat16* Vl = g_vl + (size_t)b * S_ * D_ + h * DH_;

    const int tid = threadIdx.x, lane = tid & 31, warp = tid >> 5;
    const int brow = blockIdx.x * 128;

    float4 stA[4]; uint4 stB[2];
    auto loadG = [&](int ks) {
        #pragma unroll
        for (int p = 0; p < 4; p++) {
            int row = (tid >> 3) + 32 * p, col = (tid & 7) * 4;
            stA[p] = *(const float4*)&A[(size_t)(brow + row) * S_ + ks + col];
        }
        #pragma unroll
        for (int p = 0; p < 2; p++) {
            int idx = tid + 256 * p;
            int r  = (idx & 255) >> 3;
            int ch = (idx & 7) * 8;
            const __nv_bfloat16* src = (idx < 256) ? Vh : Vl;
            stB[p] = *(const uint4*)&src[(size_t)(ks + r) * D_ + ch];
        }
    };
    auto storeS = [&]() {
        #pragma unroll
        for (int p = 0; p < 4; p++) {
            int row = (tid >> 3) + 32 * p, col = (tid & 7) * 4;
            float v[4] = {stA[p].x, stA[p].y, stA[p].z, stA[p].w};
            __nv_bfloat16 hh[4], ll[4];
            #pragma unroll
            for (int i = 0; i < 4; i++) split_bf(v[i], hh[i], ll[i]);
            *(__nv_bfloat162*)&sAh[row*40 + col]     = __halves2bfloat162(hh[0], hh[1]);
            *(__nv_bfloat162*)&sAh[row*40 + col + 2] = __halves2bfloat162(hh[2], hh[3]);
            *(__nv_bfloat162*)&sAl[row*40 + col]     = __halves2bfloat162(ll[0], ll[1]);
            *(__nv_bfloat162*)&sAl[row*40 + col + 2] = __halves2bfloat162(ll[2], ll[3]);
        }
        #pragma unroll
        for (int p = 0; p < 2; p++) {
            int idx = tid + 256 * p;
            int r  = (idx & 255) >> 3;
            int ch = (idx & 7) * 8;
            __nv_bfloat16* dst = (idx < 256) ? sBh : sBl;
            *(uint4*)&dst[r*72 + ch] = stB[p];
        }
    };

    const int wm = warp >> 1, wn = warp & 1;
    const int m0 = wm * 32, n0 = wn * 32;

    float acc[2][4][4];
    #pragma unroll
    for (int i = 0; i < 2; i++)
        #pragma unroll
        for (int j = 0; j < 4; j++)
            #pragma unroll
            for (int q = 0; q < 4; q++) acc[i][j][q] = 0.f;

    loadG(0);
    for (int ks = 0; ks < S_; ks += 32) {
        storeS();
        __syncthreads();
        if (ks + 32 < S_) loadG(ks + 32);

        #pragma unroll
        for (int kk = 0; kk < 32; kk += 16) {
            uint32_t ah[2][4], al[2][4];
            #pragma unroll
            for (int mi = 0; mi < 2; mi++) {
                int off = (m0 + mi*16 + (lane & 15)) * 40 + kk + ((lane >> 4) << 3);
                ldsm4(ah[mi], cvta_s(&sAh[off]));
                ldsm4(al[mi], cvta_s(&sAl[off]));
            }
            #pragma unroll
            for (int nj = 0; nj < 2; nj++) {
                uint32_t bh[4], bl[4];
                int off = (kk + (lane & 15)) * 72 + n0 + nj*16 + ((lane >> 4) << 3);
                ldsm4t(bh, cvta_s(&sBh[off]));
                ldsm4t(bl, cvta_s(&sBl[off]));
                #pragma unroll
                for (int mi = 0; mi < 2; mi++) {
                    mma_bf(acc[mi][2*nj],   ah[mi], bh[0], bh[1]);
                    mma_bf(acc[mi][2*nj],   ah[mi], bl[0], bl[1]);
                    mma_bf(acc[mi][2*nj],   al[mi], bh[0], bh[1]);
                    mma_bf(acc[mi][2*nj+1], ah[mi], bh[2], bh[3]);
                    mma_bf(acc[mi][2*nj+1], ah[mi], bl[2], bl[3]);
                    mma_bf(acc[mi][2*nj+1], al[mi], bh[2], bh[3]);
                }
            }
        }
        __syncthreads();
    }

    __nv_bfloat16* Ch = g_ch + (size_t)b * S_ * D_ + h * DH_;
    __nv_bfloat16* Cl = g_cl + (size_t)b * S_ * D_ + h * DH_;
    #pragma unroll
    for (int mi = 0; mi < 2; mi++) {
        int r0 = brow + m0 + mi*16 + (lane >> 2);
        #pragma unroll
        for (int nj = 0; nj < 4; nj++) {
            int c = n0 + nj*8 + (lane & 3)*2;
            __nv_bfloat16 h0,l0,h1,l1,h2,l2,h3,l3;
            split_bf(acc[mi][nj][0], h0, l0); split_bf(acc[mi][nj][1], h1, l1);
            split_bf(acc[mi][nj][2], h2, l2); split_bf(acc[mi][nj][3], h3, l3);
            *(__nv_bfloat162*)&Ch[(size_t)r0*D_ + c]     = __halves2bfloat162(h0, h1);
            *(__nv_bfloat162*)&Cl[(size_t)r0*D_ + c]     = __halves2bfloat162(l0, l1);
            *(__nv_bfloat162*)&Ch[(size_t)(r0+8)*D_ + c] = __halves2bfloat162(h2, h3);
            *(__nv_bfloat162*)&Cl[(size_t)(r0+8)*D_ + c] = __halves2bfloat162(l2, l3);
        }
    }
}

// ---------------------------------------------------------------------------
extern "C" void kernel_launch(void* const* d_in, const int* in_sizes, int n_in,
                              void* d_out, int out_size)
{
    const float* q    = (const float*)d_in[0];
    const float* k    = (const float*)d_in[1];
    const float* v    = (const float*)d_in[2];
    const float* mask = (const float*)d_in[3];
    const float* wq = (const float*)d_in[4];  const float* bq = (const float*)d_in[5];
    const float* wk = (const float*)d_in[6];  const float* bk = (const float*)d_in[7];
    const float* wv = (const float*)d_in[8];  const float* bv = (const float*)d_in[9];
    const float* wo = (const float*)d_in[10]; const float* bo = (const float*)d_in[11];
    const float* g1 = (const float*)d_in[12]; const float* be1 = (const float*)d_in[13];
    const float* mm1 = (const float*)d_in[14]; const float* mv1 = (const float*)d_in[15];
    const float* g2 = (const float*)d_in[16]; const float* be2 = (const float*)d_in[17];
    const float* mm2 = (const float*)d_in[18]; const float* mv2 = (const float*)d_in[19];
    const float* g3 = (const float*)d_in[20]; const float* be3 = (const float*)d_in[21];
    const float* mm3 = (const float*)d_in[22]; const float* mv3 = (const float*)d_in[23];

    float* out  = (float*)d_out;
    float* attn = out + (size_t)M_ * D_;

    void* p;
    __nv_bfloat16 *qh,*ql,*kh,*kl,*vh,*vl,*ch,*cl;
    __nv_bfloat16 *rqh,*rql,*rkh,*rkl,*rvh,*rvl,*wph,*wpl;
    cudaGetSymbolAddress(&p, g_qh); qh = (__nv_bfloat16*)p;
    cudaGetSymbolAddress(&p, g_ql); ql = (__nv_bfloat16*)p;
    cudaGetSymbolAddress(&p, g_kh); kh = (__nv_bfloat16*)p;
    cudaGetSymbolAddress(&p, g_kl); kl = (__nv_bfloat16*)p;
    cudaGetSymbolAddress(&p, g_vh); vh = (__nv_bfloat16*)p;
    cudaGetSymbolAddress(&p, g_vl); vl = (__nv_bfloat16*)p;
    cudaGetSymbolAddress(&p, g_ch); ch = (__nv_bfloat16*)p;
    cudaGetSymbolAddress(&p, g_cl); cl = (__nv_bfloat16*)p;
    cudaGetSymbolAddress(&p, g_rqh); rqh = (__nv_bfloat16*)p;
    cudaGetSymbolAddress(&p, g_rql); rql = (__nv_bfloat16*)p;
    cudaGetSymbolAddress(&p, g_rkh); rkh = (__nv_bfloat16*)p;
    cudaGetSymbolAddress(&p, g_rkl); rkl = (__nv_bfloat16*)p;
    cudaGetSymbolAddress(&p, g_rvh); rvh = (__nv_bfloat16*)p;
    cudaGetSymbolAddress(&p, g_rvl); rvl = (__nv_bfloat16*)p;
    cudaGetSymbolAddress(&p, g_wh); wph = (__nv_bfloat16*)p;
    cudaGetSymbolAddress(&p, g_wl); wpl = (__nv_bfloat16*)p;

    const size_t WSZ = (size_t)D_ * D_;
    const int n4a = (int)((size_t)M_ * D_ / 4);   // 2,097,152
    const int n4w = (int)(WSZ / 4);               // 262,144

    // pre-split inputs + weights
    split_kernel<<<n4a/256, 256>>>(q, rqh, rql, n4a);
    split_kernel<<<n4a/256, 256>>>(k, rkh, rkl, n4a);
    split_kernel<<<n4a/256, 256>>>(v, rvh, rvl, n4a);
    split_kernel<<<n4w/256, 256>>>(wq, wph + 0*WSZ, wpl + 0*WSZ, n4w);
    split_kernel<<<n4w/256, 256>>>(wk, wph + 1*WSZ, wpl + 1*WSZ, n4w);
    split_kernel<<<n4w/256, 256>>>(wv, wph + 2*WSZ, wpl + 2*WSZ, n4w);
    split_kernel<<<n4w/256, 256>>>(wo, wph + 3*WSZ, wpl + 3*WSZ, n4w);

    cudaFuncSetAttribute(gemm_tc2<true,true>,
        cudaFuncAttributeMaxDynamicSharedMemorySize, 2*STG_*2);
    cudaFuncSetAttribute(gemm_tc2<false,false>,
        cudaFuncAttributeMaxDynamicSharedMemorySize, 2*STG_*2);
    cudaFuncSetAttribute(scores_tc, cudaFuncAttributeMaxDynamicSharedMemorySize, 73728);

    dim3 gp(D_/128, M_/128);   // (8, 64)
    gemm_tc2<true,true><<<gp,256,2*STG_*2>>>(rqh, rql, wph + 0*WSZ, wpl + 0*WSZ,
        bq, g1, be1, mm1, mv1, nullptr, qh, ql);
    gemm_tc2<true,true><<<gp,256,2*STG_*2>>>(rkh, rkl, wph + 1*WSZ, wpl + 1*WSZ,
        bk, g2, be2, mm2, mv2, nullptr, kh, kl);
    gemm_tc2<true,true><<<gp,256,2*STG_*2>>>(rvh, rvl, wph + 2*WSZ, wpl + 2*WSZ,
        bv, g3, be3, mm3, mv3, nullptr, vh, vl);

    scores_tc<<<dim3(8,8,128),256,73728>>>(mask, attn);

    softmax_kernel<<<(unsigned)((size_t)B_*H_*S_),128>>>(attn);

    ctx_tc<<<dim3(8,128),256>>>(attn);

    gemm_tc2<false,false><<<gp,256,2*STG_*2>>>(ch, cl, wph + 3*WSZ, wpl + 3*WSZ,
        bo, nullptr, nullptr, nullptr, nullptr, out, nullptr, nullptr);
}